// round 17
// baseline (speedup 1.0000x reference)
#include <cuda_runtime.h>
#include <cuda_bf16.h>
#include <math.h>
#include <stdint.h>

// Problem constants
#define S 128
#define B 32
#define E 300
#define H 200
#define G 800      // 4*H
#define NT 1600    // 2 dirs * G
#define MROWS 4096 // S*B
#define T 17

// Scratch (device globals). H0 holds tf32 bit patterns; GI*/H1 fp32.
__device__ float g_GI0[MROWS * NT];
__device__ float g_GI1[MROWS * NT];
__device__ float g_H0[MROWS * 400];
__device__ float g_H1[MROWS * 400];

__device__ __forceinline__ float sigf(float x) { return 1.0f / (1.0f + expf(-x)); }

__device__ __forceinline__ uint32_t smem_u32(const void* p) {
    uint32_t a;
    asm("{ .reg .u64 t; cvta.to.shared.u64 t, %1; cvt.u32.u64 %0, t; }" : "=r"(a) : "l"(p));
    return a;
}
__device__ __forceinline__ void st_cluster_f32(uint32_t laddr, uint32_t rank, float v) {
    uint32_t ra;
    asm volatile("mapa.shared::cluster.u32 %0, %1, %2;" : "=r"(ra) : "r"(laddr), "r"(rank));
    asm volatile("st.shared::cluster.f32 [%0], %1;" :: "r"(ra), "f"(v) : "memory");
}
#define CL_ARRIVE() asm volatile("barrier.cluster.arrive.aligned;" ::: "memory")
#define CL_WAIT()   asm volatile("barrier.cluster.wait.aligned;" ::: "memory")
#define CLUSTER_SYNC_() do { CL_ARRIVE(); CL_WAIT(); } while (0)

__device__ __forceinline__ uint32_t f2tf32(float f) {
    uint32_t u;
    asm("cvt.rna.tf32.f32 %0, %1;" : "=r"(u) : "f"(f));
    return u;
}
__device__ __forceinline__ uint64_t fma2(uint64_t a, uint64_t b, uint64_t c) {
    uint64_t d;
    asm("fma.rn.f32x2 %0, %1, %2, %3;" : "=l"(d) : "l"(a), "l"(b), "l"(c));
    return d;
}
__device__ __forceinline__ float2 unpack2(uint64_t v) {
    uint32_t lo, hi;
    asm("mov.b64 {%0,%1}, %2;" : "=r"(lo), "=r"(hi) : "l"(v));
    return make_float2(__uint_as_float(lo), __uint_as_float(hi));
}
__device__ __forceinline__ void mma_tf32(float* c, const uint32_t* a, const uint32_t* b) {
    asm volatile(
        "mma.sync.aligned.m16n8k8.row.col.f32.tf32.tf32.f32 "
        "{%0,%1,%2,%3}, {%4,%5,%6,%7}, {%8,%9}, {%0,%1,%2,%3};"
        : "+f"(c[0]), "+f"(c[1]), "+f"(c[2]), "+f"(c[3])
        : "r"(a[0]), "r"(a[1]), "r"(a[2]), "r"(a[3]), "r"(b[0]), "r"(b[1]));
}
__device__ __forceinline__ void cpasync16(uint32_t dst, const void* src, int src_bytes) {
    asm volatile("cp.async.cg.shared.global [%0], [%1], 16, %2;"
                 :: "r"(dst), "l"(src), "r"(src_bytes) : "memory");
}
#define CP_COMMIT() asm volatile("cp.async.commit_group;" ::: "memory")
#define CP_WAIT2()  asm volatile("cp.async.wait_group 2;" ::: "memory")

// ---------------------------------------------------------------------------
// tf32 tensor-core GEMM, 4-stage cp.async pipeline, ZERO-PREP:
//  - A (layer 0): gathered straight from emb via per-row word index
//    (resolved once per loader thread, reused across all tiles).
//  - A (layer 1): g_H0 (tf32 bits produced by lstm_rec).
//  - B: straight from original Wih ([n][K] row-major) into an n-major
//    SMEM tile [64][20]; raw fp32 bits read as tf32 by mma (truncation).
// BM=128, BN=64, BK=16, 256 threads, warp tile 32x32.
// As: [128][20]; Bs: [64][20]. STG = 3840 words; 4 stages = 60 KB dyn SMEM.
// ---------------------------------------------------------------------------
#define ASZ (128 * 20)
#define BSZ (64 * 20)
#define STG (ASZ + BSZ)
#define NSTAGE 4
#define GEMM_SMEM (NSTAGE * STG * 4)
__global__ void __launch_bounds__(256) gemm_tc(const float* __restrict__ bias,
                                               int K, int layer,
                                               const int* __restrict__ words,
                                               const float* __restrict__ emb,
                                               const float* __restrict__ Wsrc) {
    float* C = layer ? g_GI1 : g_GI0;
    extern __shared__ uint32_t smd[];
    const uint32_t smbase = smem_u32(smd);

    const int tid = threadIdx.x;
    const int lane = tid & 31, wid = tid >> 5;
    const int g = lane >> 2, tg = lane & 3;
    const int warp_m = (wid & 3) * 32;
    const int warp_n = (wid >> 2) * 32;
    const int m0 = blockIdx.y * 128, n0 = blockIdx.x * 64;

    float acc[2][4][4] = {};
    const int ntiles = (K + 15) / 16;

    // loader indices: rows via tid>>2, k-chunk via tid&3 (16B each)
    const int ar0 = tid >> 2, ac = tid & 3;       // A rows 0..63
    const int ar1 = ar0 + 64;                     // A rows 64..127
    const int br = ar0;                           // B rows (n) 0..63

    // per-thread source row pointers (fixed across tiles)
    const float *arow0, *arow1;
    if (layer) {
        arow0 = g_H0 + (size_t)(m0 + ar0) * 400;
        arow1 = g_H0 + (size_t)(m0 + ar1) * 400;
    } else {
        int mm0 = m0 + ar0;
        int w0 = words[(mm0 & 31) * S + (mm0 >> 5)];
        arow0 = emb + (size_t)w0 * E;
        int mm1 = m0 + ar1;
        int w1 = words[(mm1 & 31) * S + (mm1 >> 5)];
        arow1 = emb + (size_t)w1 * E;
    }
    const float* brow = Wsrc + (size_t)(n0 + br) * K;

    auto issue = [&](int s, int k0) {
        const uint32_t st = smbase + (uint32_t)(s * STG * 4);
        int kk = k0 + ac * 4;
        int v = K - kk; v = v < 0 ? 0 : (v > 4 ? 4 : v);
        const int ko = v ? kk : 0;
        cpasync16(st + (uint32_t)((ar0 * 20 + ac * 4) * 4), arow0 + ko, v * 4);
        cpasync16(st + (uint32_t)((ar1 * 20 + ac * 4) * 4), arow1 + ko, v * 4);
        cpasync16(st + (uint32_t)((ASZ + br * 20 + ac * 4) * 4), brow + ko, v * 4);
    };

    // prologue: stages 0..2
#pragma unroll
    for (int s = 0; s < NSTAGE - 1; s++) {
        if (s < ntiles) issue(s, s * 16);
        CP_COMMIT();
    }

    for (int t = 0; t < ntiles; t++) {
        CP_WAIT2();
        __syncthreads();
        const uint32_t* As = smd + (t & 3) * STG;
        const uint32_t* Bs = As + ASZ;
#pragma unroll
        for (int k8 = 0; k8 < 16; k8 += 8) {
            uint32_t a[2][4], b[4][2];
#pragma unroll
            for (int mi = 0; mi < 2; mi++) {
                int row = warp_m + mi * 16;
                a[mi][0] = As[(row + g) * 20 + k8 + tg];
                a[mi][1] = As[(row + g + 8) * 20 + k8 + tg];
                a[mi][2] = As[(row + g) * 20 + k8 + tg + 4];
                a[mi][3] = As[(row + g + 8) * 20 + k8 + tg + 4];
            }
#pragma unroll
            for (int ni = 0; ni < 4; ni++) {
                int col = warp_n + ni * 8 + g;
                b[ni][0] = Bs[col * 20 + k8 + tg];
                b[ni][1] = Bs[col * 20 + k8 + tg + 4];
            }
#pragma unroll
            for (int mi = 0; mi < 2; mi++)
#pragma unroll
                for (int ni = 0; ni < 4; ni++)
                    mma_tf32(acc[mi][ni], a[mi], b[ni]);
        }
        const int tn = t + NSTAGE - 1;
        if (tn < ntiles) issue(tn & 3, tn * 16);
        CP_COMMIT();   // empty group at tail keeps the wait count uniform
    }

#pragma unroll
    for (int mi = 0; mi < 2; mi++) {
        int r0 = m0 + warp_m + mi * 16 + g;
        int r1 = r0 + 8;
#pragma unroll
        for (int ni = 0; ni < 4; ni++) {
            int c = n0 + warp_n + ni * 8 + tg * 2;
            float2 bv = *(const float2*)&bias[c];
            float2 o0, o1;
            o0.x = acc[mi][ni][0] + bv.x; o0.y = acc[mi][ni][1] + bv.y;
            o1.x = acc[mi][ni][2] + bv.x; o1.y = acc[mi][ni][3] + bv.y;
            *(float2*)&C[(size_t)r0 * NT + c] = o0;
            *(float2*)&C[(size_t)r1 * NT + c] = o1;
        }
    }
}

// ---------------------------------------------------------------------------
// Cluster-resident LSTM recurrence — R8 VERBATIM (best measured).
// ---------------------------------------------------------------------------
__global__ void __cluster_dims__(4, 1, 1) __launch_bounds__(224, 1)
lstm_rec(const float* __restrict__ Whh, int layer) {
    const float* GI = layer ? g_GI1 : g_GI0;
    float* Hout     = layer ? g_H1  : g_H0;
    __shared__ __align__(16) float hbuf[2 * 2 * 200];  // [ping][batch01][j]
    __shared__ __align__(16) float ag[400];            // [gate][j][batch01]

    const int tid = threadIdx.x;     // 0..223
    uint32_t crank;
    asm("mov.u32 %0, %%cluster_ctarank;" : "=r"(crank));
    const int bg = blockIdx.y >> 1;
    const int d  = blockIdx.y & 1;
    const int bb0 = bg * 2;

    const int gate = (tid < 200) ? (tid / 50) : 0;
    const int jl   = (tid < 200) ? (tid % 50) : 0;
    const int jglob = (int)crank * 50 + jl;

    const float* WhhD = Whh + (size_t)d * (G * H);

    uint64_t upair[100];
    if (tid < 200) {
        const ulonglong2* Urow =
            (const ulonglong2*)(WhhD + (size_t)(gate * 200 + jglob) * 200);
#pragma unroll
        for (int kq = 0; kq < 50; kq++) {
            ulonglong2 t = Urow[kq];
            upair[2 * kq] = t.x;
            upair[2 * kq + 1] = t.y;
        }
    }
    for (int idx = tid; idx < 800; idx += 224) hbuf[idx] = 0.0f;
    __syncthreads();
    CLUSTER_SYNC_();   // peers' hbuf zeroed before any remote h store

    const uint32_t hb_u32 = smem_u32(hbuf);
    float cst = 0.0f;
    int p = 0;

    for (int step = 0; step < 128; step++) {
        const int tstep = d ? (127 - step) : step;
        // ---- phase A: gate pre-activations ----
        if (tid < 200) {
            const float* gb = GI + (size_t)(tstep * B + bb0) * NT + d * 800
                              + gate * 200 + jglob;
            float gi0 = gb[0];
            float gi1 = gb[NT];
            const ulonglong2* hp0 = (const ulonglong2*)(hbuf + (p * 2 + 0) * 200);
            const ulonglong2* hp1 = (const ulonglong2*)(hbuf + (p * 2 + 1) * 200);
            uint64_t a00 = 0, a01 = 0, a10 = 0, a11 = 0;
#pragma unroll
            for (int kq = 0; kq < 50; kq++) {
                ulonglong2 h0 = hp0[kq];
                ulonglong2 h1 = hp1[kq];
                a00 = fma2(upair[2 * kq],     h0.x, a00);
                a01 = fma2(upair[2 * kq + 1], h0.y, a01);
                a10 = fma2(upair[2 * kq],     h1.x, a10);
                a11 = fma2(upair[2 * kq + 1], h1.y, a11);
            }
            float2 s00 = unpack2(a00), s01 = unpack2(a01);
            float2 s10 = unpack2(a10), s11 = unpack2(a11);
            ag[gate * 100 + jl * 2 + 0] = (s00.x + s00.y) + (s01.x + s01.y) + gi0;
            ag[gate * 100 + jl * 2 + 1] = (s10.x + s10.y) + (s11.x + s11.y) + gi1;
        }
        __syncthreads();
        // ---- phase B: cell update + cluster h broadcast ----
        if (tid < 100) {
            float aI = ag[tid], aF = ag[100 + tid], aG = ag[200 + tid], aO = ag[300 + tid];
            cst = sigf(aF) * cst + sigf(aI) * tanhf(aG);
            float hv = sigf(aO) * tanhf(cst);
            const int b = tid & 1, jlc = tid >> 1;
            const int jg = (int)crank * 50 + jlc;
            const int pn = p ^ 1;
            const uint32_t ha = hb_u32 + (uint32_t)((((pn * 2 + b) * 200) + jg) * 4);
            st_cluster_f32(ha, 0, hv);
            st_cluster_f32(ha, 1, hv);
            st_cluster_f32(ha, 2, hv);
            st_cluster_f32(ha, 3, hv);
            float hstore = layer ? hv : __uint_as_float(f2tf32(hv));
            Hout[(size_t)(tstep * B + bb0 + b) * 400 + d * 200 + jg] = hstore;
        }
        CLUSTER_SYNC_();  // h published cluster-wide; also fences ag reuse
        p ^= 1;
    }
}

// ---------------------------------------------------------------------------
// Output projection
// ---------------------------------------------------------------------------
__global__ void out_proj(const float* __restrict__ ow,
                         const float* __restrict__ ob, float* __restrict__ out) {
    __shared__ float x[400];
    const int m = blockIdx.x; // s*B + b
    const int tid = threadIdx.x;
    for (int i = tid; i < 400; i += blockDim.x) x[i] = g_H1[m * 400 + i];
    __syncthreads();
    if (tid < 136) {
        const int tt = tid >> 3, l = tid & 7;
        float acc = 0.0f;
        for (int k = l; k < 400; k += 8) acc = fmaf(x[k], ow[tt * 400 + k], acc);
        unsigned mask = (tid < 128) ? 0xffffffffu : 0xffu;
        acc += __shfl_down_sync(mask, acc, 4, 8);
        acc += __shfl_down_sync(mask, acc, 2, 8);
        acc += __shfl_down_sync(mask, acc, 1, 8);
        if (l == 0) {
            int s = m >> 5, b = m & 31;
            out[(b * S + s) * T + tt] = sigf(acc + ob[tt]);
        }
    }
}

// ---------------------------------------------------------------------------
extern "C" void kernel_launch(void* const* d_in, const int* in_sizes, int n_in,
                              void* d_out, int out_size) {
    const int* words = (const int*)d_in[0];
    const float* emb = (const float*)d_in[3];
    const float* Wih0 = (const float*)d_in[7];
    const float* Whh0 = (const float*)d_in[8];
    const float* b0 = (const float*)d_in[9];
    const float* Wih1 = (const float*)d_in[10];
    const float* Whh1 = (const float*)d_in[11];
    const float* b1 = (const float*)d_in[12];
    const float* ow = (const float*)d_in[13];
    const float* ob = (const float*)d_in[14];
    float* out = (float*)d_out;

    // unconditional, capture-safe host call (proven pattern)
    cudaFuncSetAttribute(gemm_tc, cudaFuncAttributeMaxDynamicSharedMemorySize,
                         GEMM_SMEM);

    // layer 0 input projection (fused embedding gather + direct-W load)
    gemm_tc<<<dim3(NT / 64, MROWS / 128), 256, GEMM_SMEM>>>(b0, 300, 0, words, emb, Wih0);
    // layer 0 recurrence
    lstm_rec<<<dim3(4, 32), 224>>>(Whh0, 0);
    // layer 1 input projection
    gemm_tc<<<dim3(NT / 64, MROWS / 128), 256, GEMM_SMEM>>>(b1, 400, 1, words, emb, Wih1);
    // layer 1 recurrence
    lstm_rec<<<dim3(4, 32), 224>>>(Whh1, 1);
    // output projection
    out_proj<<<MROWS, 160>>>(ow, ob, out);
}